// round 14
// baseline (speedup 1.0000x reference)
#include <cuda_runtime.h>
#include <cuda_bf16.h>
#include <math_constants.h>
#include <cstdint>

#define D_MODEL 1024
#define NHEADS  16
#define DHEAD   64
#define BATCH   2
#define SEQ     2048
#define KS      32
#define BHTOT   (BATCH*NHEADS)   // 32
#define MTOT    (BATCH*SEQ)      // 4096

// ---------------- scratch (static device globals; no dynamic alloc) ----------------
__device__ __align__(256) __nv_bfloat16 g_Xhi[(size_t)MTOT * D_MODEL];
__device__ __align__(256) __nv_bfloat16 g_Xmd[(size_t)MTOT * D_MODEL];
__device__ __align__(256) __nv_bfloat16 g_Xlo[(size_t)MTOT * D_MODEL];
__device__ __align__(256) __nv_bfloat16 g_Wqhi[(size_t)D_MODEL * D_MODEL];
__device__ __align__(256) __nv_bfloat16 g_Wqmd[(size_t)D_MODEL * D_MODEL];
__device__ __align__(256) __nv_bfloat16 g_Wqlo[(size_t)D_MODEL * D_MODEL];
__device__ __align__(256) __nv_bfloat16 g_Wkhi[(size_t)D_MODEL * D_MODEL];
__device__ __align__(256) __nv_bfloat16 g_Wkmd[(size_t)D_MODEL * D_MODEL];
__device__ __align__(256) __nv_bfloat16 g_Wklo[(size_t)D_MODEL * D_MODEL];
__device__ __align__(256) __nv_bfloat16 g_Qhi[(size_t)MTOT * D_MODEL];
__device__ __align__(256) __nv_bfloat16 g_Qmd[(size_t)MTOT * D_MODEL];
__device__ __align__(256) __nv_bfloat16 g_Qlo[(size_t)MTOT * D_MODEL];
__device__ __align__(256) __nv_bfloat16 g_Khi[(size_t)MTOT * D_MODEL];
__device__ __align__(256) __nv_bfloat16 g_Kmd[(size_t)MTOT * D_MODEL];
__device__ __align__(256) __nv_bfloat16 g_Klo[(size_t)MTOT * D_MODEL];
__device__ __align__(256) __nv_bfloat16 g_Wvhi[(size_t)D_MODEL * D_MODEL];
__device__ __align__(256) __nv_bfloat16 g_Wvlo[(size_t)D_MODEL * D_MODEL];
__device__ __align__(256) __nv_bfloat16 g_Wohi[(size_t)D_MODEL * D_MODEL];
__device__ __align__(256) __nv_bfloat16 g_Wolo[(size_t)D_MODEL * D_MODEL];
__device__ __align__(256) __nv_bfloat16 g_Chi[(size_t)MTOT * D_MODEL];
__device__ __align__(256) __nv_bfloat16 g_Clo[(size_t)MTOT * D_MODEL];
__device__ __align__(256) float g_V[(size_t)MTOT * D_MODEL];
__device__ __align__(256) float g_S[(size_t)BHTOT * SEQ * SEQ];   // 512 MB score scratch

// =================== baseline-PTX tensor-core helpers (sm_80-level) ===================
__device__ __forceinline__ uint32_t smem_u32(const void* p) {
    uint32_t a;
    asm("{ .reg .u64 t; cvta.to.shared.u64 t, %1; cvt.u32.u64 %0, t; }" : "=r"(a) : "l"(p));
    return a;
}
#define CP_ASYNC16(dst, src) asm volatile("cp.async.ca.shared.global [%0], [%1], 16;" :: "r"(dst), "l"(src) : "memory")
#define CP_COMMIT()          asm volatile("cp.async.commit_group;" ::: "memory")
#define CP_WAIT0()           asm volatile("cp.async.wait_group 0;" ::: "memory")
#define CP_WAIT1()           asm volatile("cp.async.wait_group 1;" ::: "memory")

__device__ __forceinline__ void ldsm4(uint32_t* r, uint32_t addr) {
    asm volatile("ldmatrix.sync.aligned.m8n8.x4.shared.b16 {%0,%1,%2,%3}, [%4];"
                 : "=r"(r[0]), "=r"(r[1]), "=r"(r[2]), "=r"(r[3]) : "r"(addr));
}
__device__ __forceinline__ void mma16816(float* c, const uint32_t* a, uint32_t b0, uint32_t b1) {
    asm volatile("mma.sync.aligned.m16n8k16.row.col.f32.bf16.bf16.f32 "
                 "{%0,%1,%2,%3}, {%4,%5,%6,%7}, {%8,%9}, {%0,%1,%2,%3};"
                 : "+f"(c[0]), "+f"(c[1]), "+f"(c[2]), "+f"(c[3])
                 : "r"(a[0]), "r"(a[1]), "r"(a[2]), "r"(a[3]), "r"(b0), "r"(b1));
}

// BK=64 smem tiles, 128B/row, 16B chunks XOR-swizzled (c ^ (r&7)).
#define SWOFF64(r, c) ((uint32_t)((r) * 128 + ((((c) ^ ((r) & 7))) << 4)))
#define A_BYTES     16384
#define STAGE_BYTES 49152
#define SMEM_GEMM   98304   // 2 stages

// ======= mma.sync mainloop: acc += sum_passes A[pa]*B[pb]^T (NT, Kd mult of 64) =======
// CTA tile 128(M) x 256(N), 256 thr, warps 2(M) x 4(N), warp tile 64x64.
// PASS ORDER: smallest-first; (h,h) last. Bit-identical arithmetic to round-13.
template<int NP>
__device__ __forceinline__ void mma_mainloop(
    const __nv_bfloat16* __restrict__ A0, const __nv_bfloat16* __restrict__ A1,
    const __nv_bfloat16* __restrict__ A2,
    const __nv_bfloat16* __restrict__ B0, const __nv_bfloat16* __restrict__ B1,
    const __nv_bfloat16* __restrict__ B2,
    int lda, int ldb, int Kd, float (&acc)[4][8][4])
{
    extern __shared__ __align__(1024) char dyn[];
    const int tid = threadIdx.x;
    const uint32_t base = smem_u32(dyn);
    const int cpp   = Kd >> 6;
    const int total = NP * cpp;

    auto issue = [&](int ch) {
        const int pi = ch / cpp;
        const int kk = (ch - pi * cpp) << 6;
        const int PA6[6] = {2, 1, 0, 1, 0, 0};
        const int PB6[6] = {0, 1, 2, 0, 1, 0};
        const int PA3[3] = {1, 0, 0};
        const int PB3[3] = {0, 1, 0};
        const int ia = (NP == 6) ? PA6[pi] : PA3[pi];
        const int ib = (NP == 6) ? PB6[pi] : PB3[pi];
        const __nv_bfloat16* Ag = (ia == 0) ? A0 : (ia == 1) ? A1 : A2;
        const __nv_bfloat16* Bg = (ib == 0) ? B0 : (ib == 1) ? B1 : B2;
        const uint32_t bo = (uint32_t)(ch & 1) * STAGE_BYTES;
#pragma unroll
        for (int i = 0; i < 4; i++) {
            const int cid = tid + (i << 8);
            const int row = cid >> 3, cc = cid & 7;
            CP_ASYNC16(base + bo + SWOFF64(row, cc),
                       (const char*)(Ag + (size_t)row * lda + kk) + (cc << 4));
        }
#pragma unroll
        for (int i = 0; i < 8; i++) {
            const int cid = tid + (i << 8);
            const int row = cid >> 3, cc = cid & 7;
            CP_ASYNC16(base + bo + A_BYTES + SWOFF64(row, cc),
                       (const char*)(Bg + (size_t)row * ldb + kk) + (cc << 4));
        }
        CP_COMMIT();
    };

    const int wid  = tid >> 5;
    const int lane = tid & 31;
    const int wm   = (wid & 1) * 64;
    const int wn   = (wid >> 1) * 64;
    const int lrow  = lane & 15;
    const int lhalf = lane >> 4;

    issue(0);
    for (int ch = 0; ch < total; ++ch) {
        if (ch + 1 < total) { issue(ch + 1); CP_WAIT1(); }
        else                { CP_WAIT0(); }
        __syncthreads();
        const uint32_t bo = (uint32_t)(ch & 1) * STAGE_BYTES;
#pragma unroll
        for (int ks = 0; ks < 4; ++ks) {
            uint32_t a[4][4], bq[4][4];
            const int col = ks * 2 + lhalf;
#pragma unroll
            for (int mt = 0; mt < 4; ++mt) {
                const int r = wm + mt * 16 + lrow;
                ldsm4(a[mt], base + bo + SWOFF64(r, col));
            }
#pragma unroll
            for (int p = 0; p < 4; ++p) {
                const int r = wn + p * 16 + lrow;
                ldsm4(bq[p], base + bo + A_BYTES + SWOFF64(r, col));
            }
#pragma unroll
            for (int mt = 0; mt < 4; ++mt)
#pragma unroll
                for (int p = 0; p < 4; ++p) {
                    mma16816(acc[mt][2 * p],     a[mt], bq[p][0], bq[p][2]);
                    mma16816(acc[mt][2 * p + 1], a[mt], bq[p][1], bq[p][3]);
                }
        }
        __syncthreads();
    }
}

__device__ __forceinline__ void split3(float v, __nv_bfloat16& h, __nv_bfloat16& m, __nv_bfloat16& l) {
    h = __float2bfloat16_rn(v);
    const float r1 = v - __bfloat162float(h);
    m = __float2bfloat16_rn(r1);
    l = __float2bfloat16_rn(r1 - __bfloat162float(m));
}

// ---------------- fused QKV projection (CTA 128x256) ----------------
__global__ __launch_bounds__(256, 1) void qkv_gemm_kernel(
    const __nv_bfloat16* __restrict__ Xh, const __nv_bfloat16* __restrict__ Xm, const __nv_bfloat16* __restrict__ Xl,
    const __nv_bfloat16* __restrict__ Wqh, const __nv_bfloat16* __restrict__ Wqm, const __nv_bfloat16* __restrict__ Wql, const float* __restrict__ bq,
    const __nv_bfloat16* __restrict__ Wkh, const __nv_bfloat16* __restrict__ Wkm, const __nv_bfloat16* __restrict__ Wkl, const float* __restrict__ bk,
    const __nv_bfloat16* __restrict__ Wvh, const __nv_bfloat16* __restrict__ Wvl, const float* __restrict__ bv,
    __nv_bfloat16* __restrict__ Qh, __nv_bfloat16* __restrict__ Qm, __nv_bfloat16* __restrict__ Ql,
    __nv_bfloat16* __restrict__ Kh, __nv_bfloat16* __restrict__ Km, __nv_bfloat16* __restrict__ Kl,
    float* __restrict__ V)
{
    const int nblk = blockIdx.x;
    const int sel  = nblk >> 2;
    const int n0   = (nblk & 3) * 256;
    const int m0   = blockIdx.y * 128;

    float acc[4][8][4] = {};
    const size_t ao  = (size_t)m0 * D_MODEL;
    const size_t bo_ = (size_t)n0 * D_MODEL;
    if (sel == 0)
        mma_mainloop<6>(Xh + ao, Xm + ao, Xl + ao, Wqh + bo_, Wqm + bo_, Wql + bo_,
                        D_MODEL, D_MODEL, D_MODEL, acc);
    else if (sel == 1)
        mma_mainloop<6>(Xh + ao, Xm + ao, Xl + ao, Wkh + bo_, Wkm + bo_, Wkl + bo_,
                        D_MODEL, D_MODEL, D_MODEL, acc);
    else
        mma_mainloop<3>(Xh + ao, Xm + ao, Xh + ao, Wvh + bo_, Wvl + bo_, Wvh + bo_,
                        D_MODEL, D_MODEL, D_MODEL, acc);

    const float* bias = (sel == 0) ? bq : (sel == 1) ? bk : bv;
    const int wid = threadIdx.x >> 5, lane = threadIdx.x & 31;
    const int wm = (wid & 1) * 64, wn = (wid >> 1) * 64;
#pragma unroll
    for (int mt = 0; mt < 4; ++mt)
#pragma unroll
        for (int nt = 0; nt < 8; ++nt) {
            const int row = m0 + wm + mt * 16 + (lane >> 2);
            const int col = n0 + wn + nt * 8 + (lane & 3) * 2;
            const float b0 = bias[col], b1 = bias[col + 1];
#pragma unroll
            for (int half = 0; half < 2; ++half) {
                const int r = row + half * 8;
                const float v0 = acc[mt][nt][2 * half + 0] + b0;
                const float v1 = acc[mt][nt][2 * half + 1] + b1;
                const size_t oi = (size_t)r * D_MODEL + col;
                if (sel == 2) {
                    float2 o = {v0, v1};
                    *(float2*)(V + oi) = o;
                } else {
                    __nv_bfloat16 h0, m0_, l0, h1, m1_, l1;
                    split3(v0, h0, m0_, l0);
                    split3(v1, h1, m1_, l1);
                    __nv_bfloat16* Ph = (sel == 0) ? Qh : Kh;
                    __nv_bfloat16* Pm = (sel == 0) ? Qm : Km;
                    __nv_bfloat16* Pl = (sel == 0) ? Ql : Kl;
                    __nv_bfloat162 hp; hp.x = h0;  hp.y = h1;
                    __nv_bfloat162 mp; mp.x = m0_; mp.y = m1_;
                    __nv_bfloat162 lp; lp.x = l0;  lp.y = l1;
                    *(__nv_bfloat162*)(Ph + oi) = hp;
                    *(__nv_bfloat162*)(Pm + oi) = mp;
                    *(__nv_bfloat162*)(Pl + oi) = lp;
                }
            }
        }
}

// ---------------- output projection: y = C @ Wo^T + bo (2-way, 3 passes) ----------------
__global__ __launch_bounds__(256, 1) void proj_gemm_kernel(
    const __nv_bfloat16* __restrict__ Chi, const __nv_bfloat16* __restrict__ Clo,
    const __nv_bfloat16* __restrict__ Wh,  const __nv_bfloat16* __restrict__ Wl,
    const float* __restrict__ bias, float* __restrict__ Y)
{
    const int m0 = blockIdx.y * 128;
    const int n0 = blockIdx.x * 256;
    float acc[4][8][4] = {};
    mma_mainloop<3>(Chi + (size_t)m0 * D_MODEL, Clo + (size_t)m0 * D_MODEL, Chi,
                    Wh + (size_t)n0 * D_MODEL, Wl + (size_t)n0 * D_MODEL, Wh,
                    D_MODEL, D_MODEL, D_MODEL, acc);

    const int wid = threadIdx.x >> 5, lane = threadIdx.x & 31;
    const int wm = (wid & 1) * 64, wn = (wid >> 1) * 64;
#pragma unroll
    for (int mt = 0; mt < 4; ++mt)
#pragma unroll
        for (int nt = 0; nt < 8; ++nt) {
            const int row = m0 + wm + mt * 16 + (lane >> 2);
            const int col = n0 + wn + nt * 8 + (lane & 3) * 2;
            const float b0 = bias[col], b1 = bias[col + 1];
#pragma unroll
            for (int half = 0; half < 2; ++half) {
                float2 o = {acc[mt][nt][2 * half] + b0, acc[mt][nt][2 * half + 1] + b1};
                *(float2*)(Y + (size_t)(row + half * 8) * D_MODEL + col) = o;
            }
        }
}

// ---------------- score GEMM: S = (Q.K^T)/8 (3-way, 6 passes), lower-tri tiles ------
__global__ __launch_bounds__(256, 1) void score_gemm_kernel(
    const __nv_bfloat16* __restrict__ Qh, const __nv_bfloat16* __restrict__ Qm, const __nv_bfloat16* __restrict__ Ql,
    const __nv_bfloat16* __restrict__ Kh, const __nv_bfloat16* __restrict__ Km, const __nv_bfloat16* __restrict__ Kl,
    float* __restrict__ S)
{
    const int jt = blockIdx.x, qt = blockIdx.y, bh = blockIdx.z;
    if (2 * jt > qt) return;
    const int b = bh >> 4, h = bh & 15;
    const size_t arow = ((size_t)b * SEQ + qt * 128) * D_MODEL + (size_t)h * DHEAD;
    const size_t brow = ((size_t)b * SEQ + jt * 256) * D_MODEL + (size_t)h * DHEAD;

    float acc[4][8][4] = {};
    mma_mainloop<6>(Qh + arow, Qm + arow, Ql + arow, Kh + brow, Km + brow, Kl + brow,
                    D_MODEL, D_MODEL, DHEAD, acc);

    const int wid = threadIdx.x >> 5, lane = threadIdx.x & 31;
    const int wm = (wid & 1) * 64, wn = (wid >> 1) * 64;
    float* Sb = S + ((size_t)bh * SEQ) * SEQ;
#pragma unroll
    for (int mt = 0; mt < 4; ++mt)
#pragma unroll
        for (int nt = 0; nt < 8; ++nt) {
            const int row = qt * 128 + wm + mt * 16 + (lane >> 2);
            const int col = jt * 256 + wn + nt * 8 + (lane & 3) * 2;
#pragma unroll
            for (int half = 0; half < 2; ++half) {
                float2 o = {acc[mt][nt][2 * half] * 0.125f, acc[mt][nt][2 * half + 1] * 0.125f};
                *(float2*)(Sb + (size_t)(row + half * 8) * SEQ + col) = o;
            }
        }
}

// ---------------- fp32 -> bf16 splits ----------------
__global__ __launch_bounds__(256) void split2_kernel(
    const float* __restrict__ src, __nv_bfloat16* __restrict__ hi,
    __nv_bfloat16* __restrict__ lo, int n)
{
    for (int i = blockIdx.x * 256 + threadIdx.x; i < n; i += gridDim.x * 256) {
        const float a = src[i];
        const __nv_bfloat16 hb = __float2bfloat16_rn(a);
        hi[i] = hb;
        lo[i] = __float2bfloat16_rn(a - __bfloat162float(hb));
    }
}
__global__ __launch_bounds__(256) void split3_kernel(
    const float* __restrict__ src, __nv_bfloat16* __restrict__ hi,
    __nv_bfloat16* __restrict__ md, __nv_bfloat16* __restrict__ lo, int n)
{
    for (int i = blockIdx.x * 256 + threadIdx.x; i < n; i += gridDim.x * 256) {
        __nv_bfloat16 h, m, l;
        split3(src[i], h, m, l);
        hi[i] = h; md[i] = m; lo[i] = l;
    }
}

// ---------------- radix-select top-32 (round-8 algorithm; warp-aggregated hist) -----
// The ONLY change vs the passing round-13 kernel: histogram atomicAdds are
// warp-aggregated via match.any (identical final counts -> identical selection).
__global__ __launch_bounds__(256) void topk_av_kernel(
    const float* __restrict__ S, const float* __restrict__ V,
    __nv_bfloat16* __restrict__ Chi, __nv_bfloat16* __restrict__ Clo,
    float* __restrict__ attn_mean)
{
    const int bid = blockIdx.x;
    const int q  = bid & (SEQ - 1);
    const int bh = bid >> 11;
    const int h  = bh & (NHEADS - 1);
    const int b  = bh >> 4;
    const int tid = threadIdx.x;
    const int lane = tid & 31;

    __shared__ unsigned keys[SEQ];
    __shared__ int hist[256];
    __shared__ int sidx[KS];
    __shared__ float pvals[KS];
    __shared__ int sh_b, sh_r, sh_all, sh_n, sh_min;

    const int nk = q + 1;
    const float* Srow = S + ((size_t)bh * SEQ + q) * SEQ;
    for (int j = tid; j < nk; j += 256) {
        unsigned bits = __float_as_uint(Srow[j]);
        keys[j] = (bits & 0x80000000u) ? ~bits : (bits | 0x80000000u);
    }
    __syncthreads();

    int ksel;
    if (nk <= KS) {
        ksel = nk;
        if (tid < nk) sidx[tid] = tid;
        __syncthreads();
    } else {
        ksel = KS;
        const int trips = (nk + 255) >> 8;     // uniform trip count across the block
        unsigned prefix = 0;
        int r = KS, s = 32, all_eq = 0;
        for (int lvl = 0; lvl < 4 && !all_eq; lvl++) {
            s -= 8;
            hist[tid] = 0;
            __syncthreads();
            for (int t = 0; t < trips; t++) {
                const int j = tid + (t << 8);
                int bin = -1;
                if (j < nk) {
                    const unsigned k = keys[j];
                    if ((unsigned)(((unsigned long long)(k ^ prefix)) >> (s + 8)) == 0u)
                        bin = (int)((k >> s) & 255u);
                }
                const unsigned grp = __match_any_sync(0xffffffffu, bin);
                if (bin >= 0 && lane == (__ffs(grp) - 1))
                    atomicAdd(&hist[bin], __popc(grp));
            }
            __syncthreads();
            if (tid == 0) {
                int acc = 0, bsel = 0, rr = r, cnt = 0;
                for (int bb = 255; bb >= 0; bb--) {
                    const int c = hist[bb];
                    if (acc + c >= r) { bsel = bb; rr = r - acc; cnt = c; break; }
                    acc += c;
                }
                sh_b = bsel; sh_r = rr;
                sh_all = (cnt == rr) ? 1 : 0;
            }
            __syncthreads();
            prefix |= ((unsigned)sh_b) << s;
            r = sh_r;
            all_eq = sh_all;
        }
        if (tid == 0) sh_n = 0;
        __syncthreads();
        const unsigned pp = prefix >> s;
        for (int j = tid; j < nk; j += 256) {
            const unsigned kp = keys[j] >> s;
            if (kp > pp || (all_eq && kp == pp)) {
                const int pos = atomicAdd(&sh_n, 1);
                sidx[pos] = j;
            }
        }
        __syncthreads();
        if (!all_eq) {
            const int base = sh_n;
            int last = -1;
            for (int t = 0; t < r; t++) {
                if (tid == 0) sh_min = 0x7FFFFFFF;
                __syncthreads();
                int lm = 0x7FFFFFFF;
                for (int j = tid; j < nk; j += 256)
                    if (j > last && (keys[j] >> s) == pp && j < lm) lm = j;
                if (lm != 0x7FFFFFFF) atomicMin(&sh_min, lm);
                __syncthreads();
                last = sh_min;
                if (tid == 0) sidx[base + t] = last;
                __syncthreads();
            }
        }
    }

    if (tid < 32) {
        float v = -CUDART_INF_F;
        if (tid < ksel) {
            const unsigned k = keys[sidx[tid]];
            const unsigned bits = (k & 0x80000000u) ? (k ^ 0x80000000u) : ~k;
            v = __uint_as_float(bits);
        }
        float m = v;
#pragma unroll
        for (int off = 16; off; off >>= 1) m = fmaxf(m, __shfl_xor_sync(0xffffffffu, m, off));
        float e = (tid < ksel) ? __expf(v - m) : 0.0f;
        float z = e;
#pragma unroll
        for (int off = 16; off; off >>= 1) z += __shfl_xor_sync(0xffffffffu, z, off);
        pvals[tid] = e / z;
    }
    __syncthreads();

    if (tid < ksel)
        atomicAdd(attn_mean + ((size_t)b * SEQ + q) * SEQ + sidx[tid],
                  pvals[tid] * (1.0f / NHEADS));

    if (tid < DHEAD) {
        float acc = 0.0f;
        for (int i = 0; i < ksel; i++)
            acc += pvals[i] * V[((size_t)b * SEQ + sidx[i]) * D_MODEL + h * DHEAD + tid];
        const size_t oi = ((size_t)b * SEQ + q) * D_MODEL + h * DHEAD + tid;
        const __nv_bfloat16 hb = __float2bfloat16_rn(acc);
        Chi[oi] = hb;
        Clo[oi] = __float2bfloat16_rn(acc - __bfloat162float(hb));
    }
}

// ---------------- launch ----------------
extern "C" void kernel_launch(void* const* d_in, const int* in_sizes, int n_in,
                              void* d_out, int out_size)
{
    (void)in_sizes; (void)n_in; (void)out_size;
    const float* x  = (const float*)d_in[0];
    const float* Wq = (const float*)d_in[1];
    const float* bq = (const float*)d_in[2];
    const float* Wk = (const float*)d_in[3];
    const float* bk = (const float*)d_in[4];
    const float* Wv = (const float*)d_in[5];
    const float* bv = (const float*)d_in[6];
    const float* Wo = (const float*)d_in[7];
    const float* bo = (const float*)d_in[8];

    float* y    = (float*)d_out;                      // [2,2048,1024]
    float* attn = y + (size_t)MTOT * D_MODEL;         // [2,2048,2048]

    static bool init = false;
    static __nv_bfloat16 *pXh, *pXm, *pXl;
    static __nv_bfloat16 *pWqh, *pWqm, *pWql, *pWkh, *pWkm, *pWkl;
    static __nv_bfloat16 *pWvh, *pWvl, *pWoh, *pWol;
    static __nv_bfloat16 *pQh, *pQm, *pQl, *pKh, *pKm, *pKl, *pCh, *pCl;
    static float *pV, *pS;
    if (!init) {
        cudaGetSymbolAddress((void**)&pXh, g_Xhi);  cudaGetSymbolAddress((void**)&pXm, g_Xmd);
        cudaGetSymbolAddress((void**)&pXl, g_Xlo);
        cudaGetSymbolAddress((void**)&pWqh, g_Wqhi); cudaGetSymbolAddress((void**)&pWqm, g_Wqmd);
        cudaGetSymbolAddress((void**)&pWql, g_Wqlo);
        cudaGetSymbolAddress((void**)&pWkh, g_Wkhi); cudaGetSymbolAddress((void**)&pWkm, g_Wkmd);
        cudaGetSymbolAddress((void**)&pWkl, g_Wklo);
        cudaGetSymbolAddress((void**)&pWvh, g_Wvhi); cudaGetSymbolAddress((void**)&pWvl, g_Wvlo);
        cudaGetSymbolAddress((void**)&pWoh, g_Wohi); cudaGetSymbolAddress((void**)&pWol, g_Wolo);
        cudaGetSymbolAddress((void**)&pQh, g_Qhi);   cudaGetSymbolAddress((void**)&pQm, g_Qmd);
        cudaGetSymbolAddress((void**)&pQl, g_Qlo);
        cudaGetSymbolAddress((void**)&pKh, g_Khi);   cudaGetSymbolAddress((void**)&pKm, g_Kmd);
        cudaGetSymbolAddress((void**)&pKl, g_Klo);
        cudaGetSymbolAddress((void**)&pCh, g_Chi);   cudaGetSymbolAddress((void**)&pCl, g_Clo);
        cudaGetSymbolAddress((void**)&pV, g_V);      cudaGetSymbolAddress((void**)&pS, g_S);
        cudaFuncSetAttribute(qkv_gemm_kernel,   cudaFuncAttributeMaxDynamicSharedMemorySize, SMEM_GEMM);
        cudaFuncSetAttribute(proj_gemm_kernel,  cudaFuncAttributeMaxDynamicSharedMemorySize, SMEM_GEMM);
        cudaFuncSetAttribute(score_gemm_kernel, cudaFuncAttributeMaxDynamicSharedMemorySize, SMEM_GEMM);
        init = true;
    }

    split3_kernel<<<2048, 256>>>(x,  pXh, pXm, pXl, MTOT * D_MODEL);
    split3_kernel<<<2048, 256>>>(Wq, pWqh, pWqm, pWql, D_MODEL * D_MODEL);
    split3_kernel<<<2048, 256>>>(Wk, pWkh, pWkm, pWkl, D_MODEL * D_MODEL);
    split2_kernel<<<2048, 256>>>(Wv, pWvh, pWvl, D_MODEL * D_MODEL);
    split2_kernel<<<2048, 256>>>(Wo, pWoh, pWol, D_MODEL * D_MODEL);

    qkv_gemm_kernel<<<dim3(12, MTOT / 128), 256, SMEM_GEMM>>>(
        pXh, pXm, pXl,
        pWqh, pWqm, pWql, bq,
        pWkh, pWkm, pWkl, bk,
        pWvh, pWvl, bv,
        pQh, pQm, pQl, pKh, pKm, pKl, pV);

    score_gemm_kernel<<<dim3(SEQ / 256, SEQ / 128, BHTOT), 256, SMEM_GEMM>>>(
        pQh, pQm, pQl, pKh, pKm, pKl, pS);

    cudaMemsetAsync(attn, 0, (size_t)BATCH * SEQ * SEQ * sizeof(float));

    topk_av_kernel<<<BATCH * NHEADS * SEQ, 256>>>(pS, pV, pCh, pCl, attn);

    proj_gemm_kernel<<<dim3(D_MODEL / 256, MTOT / 128), 256, SMEM_GEMM>>>(
        pCh, pCl, pWoh, pWol, bo, y);
}

// round 17
// speedup vs baseline: 1.0707x; 1.0707x over previous
#include <cuda_runtime.h>
#include <cuda_bf16.h>
#include <math_constants.h>
#include <cstdint>

#define D_MODEL 1024
#define NHEADS  16
#define DHEAD   64
#define BATCH   2
#define SEQ     2048
#define KS      32
#define BHTOT   (BATCH*NHEADS)   // 32
#define MTOT    (BATCH*SEQ)      // 4096

// ---------------- scratch (static device globals; no dynamic alloc) ----------------
__device__ __align__(256) __nv_bfloat16 g_Xhi[(size_t)MTOT * D_MODEL];
__device__ __align__(256) __nv_bfloat16 g_Xmd[(size_t)MTOT * D_MODEL];
__device__ __align__(256) __nv_bfloat16 g_Xlo[(size_t)MTOT * D_MODEL];
__device__ __align__(256) __nv_bfloat16 g_Wqhi[(size_t)D_MODEL * D_MODEL];
__device__ __align__(256) __nv_bfloat16 g_Wqmd[(size_t)D_MODEL * D_MODEL];
__device__ __align__(256) __nv_bfloat16 g_Wqlo[(size_t)D_MODEL * D_MODEL];
__device__ __align__(256) __nv_bfloat16 g_Wkhi[(size_t)D_MODEL * D_MODEL];
__device__ __align__(256) __nv_bfloat16 g_Wkmd[(size_t)D_MODEL * D_MODEL];
__device__ __align__(256) __nv_bfloat16 g_Wklo[(size_t)D_MODEL * D_MODEL];
__device__ __align__(256) __nv_bfloat16 g_Qhi[(size_t)MTOT * D_MODEL];
__device__ __align__(256) __nv_bfloat16 g_Qmd[(size_t)MTOT * D_MODEL];
__device__ __align__(256) __nv_bfloat16 g_Qlo[(size_t)MTOT * D_MODEL];
__device__ __align__(256) __nv_bfloat16 g_Khi[(size_t)MTOT * D_MODEL];
__device__ __align__(256) __nv_bfloat16 g_Kmd[(size_t)MTOT * D_MODEL];
__device__ __align__(256) __nv_bfloat16 g_Klo[(size_t)MTOT * D_MODEL];
__device__ __align__(256) __nv_bfloat16 g_Wvhi[(size_t)D_MODEL * D_MODEL];
__device__ __align__(256) __nv_bfloat16 g_Wvlo[(size_t)D_MODEL * D_MODEL];
__device__ __align__(256) __nv_bfloat16 g_Wohi[(size_t)D_MODEL * D_MODEL];
__device__ __align__(256) __nv_bfloat16 g_Wolo[(size_t)D_MODEL * D_MODEL];
__device__ __align__(256) __nv_bfloat16 g_Chi[(size_t)MTOT * D_MODEL];
__device__ __align__(256) __nv_bfloat16 g_Clo[(size_t)MTOT * D_MODEL];
__device__ __align__(256) float g_V[(size_t)MTOT * D_MODEL];
__device__ __align__(256) float g_S[(size_t)BHTOT * SEQ * SEQ];   // 512 MB score scratch

// =================== baseline-PTX tensor-core helpers (sm_80-level) ===================
__device__ __forceinline__ uint32_t smem_u32(const void* p) {
    uint32_t a;
    asm("{ .reg .u64 t; cvta.to.shared.u64 t, %1; cvt.u32.u64 %0, t; }" : "=r"(a) : "l"(p));
    return a;
}
#define CP_ASYNC16(dst, src) asm volatile("cp.async.ca.shared.global [%0], [%1], 16;" :: "r"(dst), "l"(src) : "memory")
#define CP_COMMIT()          asm volatile("cp.async.commit_group;" ::: "memory")
#define CP_WAIT0()           asm volatile("cp.async.wait_group 0;" ::: "memory")
#define CP_WAIT1()           asm volatile("cp.async.wait_group 1;" ::: "memory")

__device__ __forceinline__ void ldsm4(uint32_t* r, uint32_t addr) {
    asm volatile("ldmatrix.sync.aligned.m8n8.x4.shared.b16 {%0,%1,%2,%3}, [%4];"
                 : "=r"(r[0]), "=r"(r[1]), "=r"(r[2]), "=r"(r[3]) : "r"(addr));
}
__device__ __forceinline__ void mma16816(float* c, const uint32_t* a, uint32_t b0, uint32_t b1) {
    asm volatile("mma.sync.aligned.m16n8k16.row.col.f32.bf16.bf16.f32 "
                 "{%0,%1,%2,%3}, {%4,%5,%6,%7}, {%8,%9}, {%0,%1,%2,%3};"
                 : "+f"(c[0]), "+f"(c[1]), "+f"(c[2]), "+f"(c[3])
                 : "r"(a[0]), "r"(a[1]), "r"(a[2]), "r"(a[3]), "r"(b0), "r"(b1));
}

// BK=64 smem tiles, 128B/row, 16B chunks XOR-swizzled (c ^ (r&7)).
#define SWOFF64(r, c) ((uint32_t)((r) * 128 + ((((c) ^ ((r) & 7))) << 4)))
#define A_BYTES     16384
#define STAGE_BYTES 49152
#define SMEM_GEMM   98304   // 2 stages

// ======= mma.sync mainloop: acc += sum_passes A[pa]*B[pb]^T (NT, Kd mult of 64) =======
// CTA tile 128(M) x 256(N), 256 thr, warps 2(M) x 4(N), warp tile 64x64.
// PASS ORDER: smallest-first; (h,h) last. Bit-identical arithmetic to round-13.
template<int NP>
__device__ __forceinline__ void mma_mainloop(
    const __nv_bfloat16* __restrict__ A0, const __nv_bfloat16* __restrict__ A1,
    const __nv_bfloat16* __restrict__ A2,
    const __nv_bfloat16* __restrict__ B0, const __nv_bfloat16* __restrict__ B1,
    const __nv_bfloat16* __restrict__ B2,
    int lda, int ldb, int Kd, float (&acc)[4][8][4])
{
    extern __shared__ __align__(1024) char dyn[];
    const int tid = threadIdx.x;
    const uint32_t base = smem_u32(dyn);
    const int cpp   = Kd >> 6;
    const int total = NP * cpp;

    auto issue = [&](int ch) {
        const int pi = ch / cpp;
        const int kk = (ch - pi * cpp) << 6;
        const int PA6[6] = {2, 1, 0, 1, 0, 0};
        const int PB6[6] = {0, 1, 2, 0, 1, 0};
        const int PA3[3] = {1, 0, 0};
        const int PB3[3] = {0, 1, 0};
        const int ia = (NP == 6) ? PA6[pi] : PA3[pi];
        const int ib = (NP == 6) ? PB6[pi] : PB3[pi];
        const __nv_bfloat16* Ag = (ia == 0) ? A0 : (ia == 1) ? A1 : A2;
        const __nv_bfloat16* Bg = (ib == 0) ? B0 : (ib == 1) ? B1 : B2;
        const uint32_t bo = (uint32_t)(ch & 1) * STAGE_BYTES;
#pragma unroll
        for (int i = 0; i < 4; i++) {
            const int cid = tid + (i << 8);
            const int row = cid >> 3, cc = cid & 7;
            CP_ASYNC16(base + bo + SWOFF64(row, cc),
                       (const char*)(Ag + (size_t)row * lda + kk) + (cc << 4));
        }
#pragma unroll
        for (int i = 0; i < 8; i++) {
            const int cid = tid + (i << 8);
            const int row = cid >> 3, cc = cid & 7;
            CP_ASYNC16(base + bo + A_BYTES + SWOFF64(row, cc),
                       (const char*)(Bg + (size_t)row * ldb + kk) + (cc << 4));
        }
        CP_COMMIT();
    };

    const int wid  = tid >> 5;
    const int lane = tid & 31;
    const int wm   = (wid & 1) * 64;
    const int wn   = (wid >> 1) * 64;
    const int lrow  = lane & 15;
    const int lhalf = lane >> 4;

    issue(0);
    for (int ch = 0; ch < total; ++ch) {
        if (ch + 1 < total) { issue(ch + 1); CP_WAIT1(); }
        else                { CP_WAIT0(); }
        __syncthreads();
        const uint32_t bo = (uint32_t)(ch & 1) * STAGE_BYTES;
#pragma unroll
        for (int ks = 0; ks < 4; ++ks) {
            uint32_t a[4][4], bq[4][4];
            const int col = ks * 2 + lhalf;
#pragma unroll
            for (int mt = 0; mt < 4; ++mt) {
                const int r = wm + mt * 16 + lrow;
                ldsm4(a[mt], base + bo + SWOFF64(r, col));
            }
#pragma unroll
            for (int p = 0; p < 4; ++p) {
                const int r = wn + p * 16 + lrow;
                ldsm4(bq[p], base + bo + A_BYTES + SWOFF64(r, col));
            }
#pragma unroll
            for (int mt = 0; mt < 4; ++mt)
#pragma unroll
                for (int p = 0; p < 4; ++p) {
                    mma16816(acc[mt][2 * p],     a[mt], bq[p][0], bq[p][2]);
                    mma16816(acc[mt][2 * p + 1], a[mt], bq[p][1], bq[p][3]);
                }
        }
        __syncthreads();
    }
}

__device__ __forceinline__ void split3(float v, __nv_bfloat16& h, __nv_bfloat16& m, __nv_bfloat16& l) {
    h = __float2bfloat16_rn(v);
    const float r1 = v - __bfloat162float(h);
    m = __float2bfloat16_rn(r1);
    l = __float2bfloat16_rn(r1 - __bfloat162float(m));
}

// ---------------- fused QKV projection (CTA 128x256) ----------------
__global__ __launch_bounds__(256, 1) void qkv_gemm_kernel(
    const __nv_bfloat16* __restrict__ Xh, const __nv_bfloat16* __restrict__ Xm, const __nv_bfloat16* __restrict__ Xl,
    const __nv_bfloat16* __restrict__ Wqh, const __nv_bfloat16* __restrict__ Wqm, const __nv_bfloat16* __restrict__ Wql, const float* __restrict__ bq,
    const __nv_bfloat16* __restrict__ Wkh, const __nv_bfloat16* __restrict__ Wkm, const __nv_bfloat16* __restrict__ Wkl, const float* __restrict__ bk,
    const __nv_bfloat16* __restrict__ Wvh, const __nv_bfloat16* __restrict__ Wvl, const float* __restrict__ bv,
    __nv_bfloat16* __restrict__ Qh, __nv_bfloat16* __restrict__ Qm, __nv_bfloat16* __restrict__ Ql,
    __nv_bfloat16* __restrict__ Kh, __nv_bfloat16* __restrict__ Km, __nv_bfloat16* __restrict__ Kl,
    float* __restrict__ V)
{
    const int nblk = blockIdx.x;
    const int sel  = nblk >> 2;
    const int n0   = (nblk & 3) * 256;
    const int m0   = blockIdx.y * 128;

    float acc[4][8][4] = {};
    const size_t ao  = (size_t)m0 * D_MODEL;
    const size_t bo_ = (size_t)n0 * D_MODEL;
    if (sel == 0)
        mma_mainloop<6>(Xh + ao, Xm + ao, Xl + ao, Wqh + bo_, Wqm + bo_, Wql + bo_,
                        D_MODEL, D_MODEL, D_MODEL, acc);
    else if (sel == 1)
        mma_mainloop<6>(Xh + ao, Xm + ao, Xl + ao, Wkh + bo_, Wkm + bo_, Wkl + bo_,
                        D_MODEL, D_MODEL, D_MODEL, acc);
    else
        mma_mainloop<3>(Xh + ao, Xm + ao, Xh + ao, Wvh + bo_, Wvl + bo_, Wvh + bo_,
                        D_MODEL, D_MODEL, D_MODEL, acc);

    const float* bias = (sel == 0) ? bq : (sel == 1) ? bk : bv;
    const int wid = threadIdx.x >> 5, lane = threadIdx.x & 31;
    const int wm = (wid & 1) * 64, wn = (wid >> 1) * 64;
#pragma unroll
    for (int mt = 0; mt < 4; ++mt)
#pragma unroll
        for (int nt = 0; nt < 8; ++nt) {
            const int row = m0 + wm + mt * 16 + (lane >> 2);
            const int col = n0 + wn + nt * 8 + (lane & 3) * 2;
            const float b0 = bias[col], b1 = bias[col + 1];
#pragma unroll
            for (int half = 0; half < 2; ++half) {
                const int r = row + half * 8;
                const float v0 = acc[mt][nt][2 * half + 0] + b0;
                const float v1 = acc[mt][nt][2 * half + 1] + b1;
                const size_t oi = (size_t)r * D_MODEL + col;
                if (sel == 2) {
                    float2 o = {v0, v1};
                    *(float2*)(V + oi) = o;
                } else {
                    __nv_bfloat16 h0, m0_, l0, h1, m1_, l1;
                    split3(v0, h0, m0_, l0);
                    split3(v1, h1, m1_, l1);
                    __nv_bfloat16* Ph = (sel == 0) ? Qh : Kh;
                    __nv_bfloat16* Pm = (sel == 0) ? Qm : Km;
                    __nv_bfloat16* Pl = (sel == 0) ? Ql : Kl;
                    __nv_bfloat162 hp; hp.x = h0;  hp.y = h1;
                    __nv_bfloat162 mp; mp.x = m0_; mp.y = m1_;
                    __nv_bfloat162 lp; lp.x = l0;  lp.y = l1;
                    *(__nv_bfloat162*)(Ph + oi) = hp;
                    *(__nv_bfloat162*)(Pm + oi) = mp;
                    *(__nv_bfloat162*)(Pl + oi) = lp;
                }
            }
        }
}

// ---------------- output projection: y = C @ Wo^T + bo (2-way, 3 passes) ----------------
__global__ __launch_bounds__(256, 1) void proj_gemm_kernel(
    const __nv_bfloat16* __restrict__ Chi, const __nv_bfloat16* __restrict__ Clo,
    const __nv_bfloat16* __restrict__ Wh,  const __nv_bfloat16* __restrict__ Wl,
    const float* __restrict__ bias, float* __restrict__ Y)
{
    const int m0 = blockIdx.y * 128;
    const int n0 = blockIdx.x * 256;
    float acc[4][8][4] = {};
    mma_mainloop<3>(Chi + (size_t)m0 * D_MODEL, Clo + (size_t)m0 * D_MODEL, Chi,
                    Wh + (size_t)n0 * D_MODEL, Wl + (size_t)n0 * D_MODEL, Wh,
                    D_MODEL, D_MODEL, D_MODEL, acc);

    const int wid = threadIdx.x >> 5, lane = threadIdx.x & 31;
    const int wm = (wid & 1) * 64, wn = (wid >> 1) * 64;
#pragma unroll
    for (int mt = 0; mt < 4; ++mt)
#pragma unroll
        for (int nt = 0; nt < 8; ++nt) {
            const int row = m0 + wm + mt * 16 + (lane >> 2);
            const int col = n0 + wn + nt * 8 + (lane & 3) * 2;
            const float b0 = bias[col], b1 = bias[col + 1];
#pragma unroll
            for (int half = 0; half < 2; ++half) {
                float2 o = {acc[mt][nt][2 * half] + b0, acc[mt][nt][2 * half + 1] + b1};
                *(float2*)(Y + (size_t)(row + half * 8) * D_MODEL + col) = o;
            }
        }
}

// ---------------- score GEMM: S = (Q.K^T)/8 (3-way, 6 passes), lower-tri tiles ------
__global__ __launch_bounds__(256, 1) void score_gemm_kernel(
    const __nv_bfloat16* __restrict__ Qh, const __nv_bfloat16* __restrict__ Qm, const __nv_bfloat16* __restrict__ Ql,
    const __nv_bfloat16* __restrict__ Kh, const __nv_bfloat16* __restrict__ Km, const __nv_bfloat16* __restrict__ Kl,
    float* __restrict__ S)
{
    const int jt = blockIdx.x, qt = blockIdx.y, bh = blockIdx.z;
    if (2 * jt > qt) return;
    const int b = bh >> 4, h = bh & 15;
    const size_t arow = ((size_t)b * SEQ + qt * 128) * D_MODEL + (size_t)h * DHEAD;
    const size_t brow = ((size_t)b * SEQ + jt * 256) * D_MODEL + (size_t)h * DHEAD;

    float acc[4][8][4] = {};
    mma_mainloop<6>(Qh + arow, Qm + arow, Ql + arow, Kh + brow, Km + brow, Kl + brow,
                    D_MODEL, D_MODEL, DHEAD, acc);

    const int wid = threadIdx.x >> 5, lane = threadIdx.x & 31;
    const int wm = (wid & 1) * 64, wn = (wid >> 1) * 64;
    float* Sb = S + ((size_t)bh * SEQ) * SEQ;
#pragma unroll
    for (int mt = 0; mt < 4; ++mt)
#pragma unroll
        for (int nt = 0; nt < 8; ++nt) {
            const int row = qt * 128 + wm + mt * 16 + (lane >> 2);
            const int col = jt * 256 + wn + nt * 8 + (lane & 3) * 2;
#pragma unroll
            for (int half = 0; half < 2; ++half) {
                float2 o = {acc[mt][nt][2 * half] * 0.125f, acc[mt][nt][2 * half + 1] * 0.125f};
                *(float2*)(Sb + (size_t)(row + half * 8) * SEQ + col) = o;
            }
        }
}

// ---------------- fp32 -> bf16 splits ----------------
__global__ __launch_bounds__(256) void split2_kernel(
    const float* __restrict__ src, __nv_bfloat16* __restrict__ hi,
    __nv_bfloat16* __restrict__ lo, int n)
{
    for (int i = blockIdx.x * 256 + threadIdx.x; i < n; i += gridDim.x * 256) {
        const float a = src[i];
        const __nv_bfloat16 hb = __float2bfloat16_rn(a);
        hi[i] = hb;
        lo[i] = __float2bfloat16_rn(a - __bfloat162float(hb));
    }
}
__global__ __launch_bounds__(256) void split3_kernel(
    const float* __restrict__ src, __nv_bfloat16* __restrict__ hi,
    __nv_bfloat16* __restrict__ md, __nv_bfloat16* __restrict__ lo, int n)
{
    for (int i = blockIdx.x * 256 + threadIdx.x; i < n; i += gridDim.x * 256) {
        __nv_bfloat16 h, m, l;
        split3(src[i], h, m, l);
        hi[i] = h; md[i] = m; lo[i] = l;
    }
}

// ---------------- radix-select top-32 (select path = ROUND-13 EXACT) ----------------
// Only change vs round-13: the sparse A·V epilogue uses all 8 warps (4 groups of 64
// lanes + smem partial reduction) instead of 64 threads. Pure float reassociation.
__global__ __launch_bounds__(256) void topk_av_kernel(
    const float* __restrict__ S, const float* __restrict__ V,
    __nv_bfloat16* __restrict__ Chi, __nv_bfloat16* __restrict__ Clo,
    float* __restrict__ attn_mean)
{
    const int bid = blockIdx.x;
    const int q  = bid & (SEQ - 1);
    const int bh = bid >> 11;
    const int h  = bh & (NHEADS - 1);
    const int b  = bh >> 4;
    const int tid = threadIdx.x;

    __shared__ unsigned keys[SEQ];
    __shared__ int hist[256];
    __shared__ int sidx[KS];
    __shared__ float pvals[KS];
    __shared__ float part[4][DHEAD];
    __shared__ int sh_b, sh_r, sh_all, sh_n, sh_min;

    const int nk = q + 1;
    const float* Srow = S + ((size_t)bh * SEQ + q) * SEQ;
    for (int j = tid; j < nk; j += 256) {
        unsigned bits = __float_as_uint(Srow[j]);
        keys[j] = (bits & 0x80000000u) ? ~bits : (bits | 0x80000000u);
    }
    __syncthreads();

    int ksel;
    if (nk <= KS) {
        ksel = nk;
        if (tid < nk) sidx[tid] = tid;
        __syncthreads();
    } else {
        ksel = KS;
        unsigned prefix = 0;
        int r = KS, s = 32, all_eq = 0;
        for (int lvl = 0; lvl < 4 && !all_eq; lvl++) {
            s -= 8;
            hist[tid] = 0;
            __syncthreads();
            for (int j = tid; j < nk; j += 256) {
                const unsigned k = keys[j];
                if ((unsigned)(((unsigned long long)(k ^ prefix)) >> (s + 8)) == 0u)
                    atomicAdd(&hist[(k >> s) & 255], 1);
            }
            __syncthreads();
            if (tid == 0) {
                int acc = 0, bsel = 0, rr = r, cnt = 0;
                for (int bb = 255; bb >= 0; bb--) {
                    const int c = hist[bb];
                    if (acc + c >= r) { bsel = bb; rr = r - acc; cnt = c; break; }
                    acc += c;
                }
                sh_b = bsel; sh_r = rr;
                sh_all = (cnt == rr) ? 1 : 0;
            }
            __syncthreads();
            prefix |= ((unsigned)sh_b) << s;
            r = sh_r;
            all_eq = sh_all;
        }
        if (tid == 0) sh_n = 0;
        __syncthreads();
        const unsigned pp = prefix >> s;
        for (int j = tid; j < nk; j += 256) {
            const unsigned kp = keys[j] >> s;
            if (kp > pp || (all_eq && kp == pp)) {
                const int pos = atomicAdd(&sh_n, 1);
                sidx[pos] = j;
            }
        }
        __syncthreads();
        if (!all_eq) {
            const int base = sh_n;
            int last = -1;
            for (int t = 0; t < r; t++) {
                if (tid == 0) sh_min = 0x7FFFFFFF;
                __syncthreads();
                int lm = 0x7FFFFFFF;
                for (int j = tid; j < nk; j += 256)
                    if (j > last && (keys[j] >> s) == pp && j < lm) lm = j;
                if (lm != 0x7FFFFFFF) atomicMin(&sh_min, lm);
                __syncthreads();
                last = sh_min;
                if (tid == 0) sidx[base + t] = last;
                __syncthreads();
            }
        }
    }

    if (tid < 32) {
        float v = -CUDART_INF_F;
        if (tid < ksel) {
            const unsigned k = keys[sidx[tid]];
            const unsigned bits = (k & 0x80000000u) ? (k ^ 0x80000000u) : ~k;
            v = __uint_as_float(bits);
        }
        float m = v;
#pragma unroll
        for (int off = 16; off; off >>= 1) m = fmaxf(m, __shfl_xor_sync(0xffffffffu, m, off));
        float e = (tid < ksel) ? __expf(v - m) : 0.0f;
        float z = e;
#pragma unroll
        for (int off = 16; off; off >>= 1) z += __shfl_xor_sync(0xffffffffu, z, off);
        pvals[tid] = e / z;
    }
    __syncthreads();

    if (tid < ksel)
        atomicAdd(attn_mean + ((size_t)b * SEQ + q) * SEQ + sidx[tid],
                  pvals[tid] * (1.0f / NHEADS));

    // sparse attn @ V across all 8 warps: 4 groups of 64 lanes, then reduce
    {
        const int grp = tid >> 6, l64 = tid & 63;
        float acc = 0.0f;
        for (int i = grp; i < ksel; i += 4)
            acc += pvals[i] * V[((size_t)b * SEQ + sidx[i]) * D_MODEL + h * DHEAD + l64];
        part[grp][l64] = acc;
    }
    __syncthreads();
    if (tid < DHEAD) {
        const float acc = part[0][tid] + part[1][tid] + part[2][tid] + part[3][tid];
        const size_t oi = ((size_t)b * SEQ + q) * D_MODEL + h * DHEAD + tid;
        const __nv_bfloat16 hb = __float2bfloat16_rn(acc);
        Chi[oi] = hb;
        Clo[oi] = __float2bfloat16_rn(acc - __bfloat162float(hb));
    }
}

// ---------------- launch ----------------
extern "C" void kernel_launch(void* const* d_in, const int* in_sizes, int n_in,
                              void* d_out, int out_size)
{
    (void)in_sizes; (void)n_in; (void)out_size;
    const float* x  = (const float*)d_in[0];
    const float* Wq = (const float*)d_in[1];
    const float* bq = (const float*)d_in[2];
    const float* Wk = (const float*)d_in[3];
    const float* bk = (const float*)d_in[4];
    const float* Wv = (const float*)d_in[5];
    const float* bv = (const float*)d_in[6];
    const float* Wo = (const float*)d_in[7];
    const float* bo = (const float*)d_in[8];

    float* y    = (float*)d_out;                      // [2,2048,1024]
    float* attn = y + (size_t)MTOT * D_MODEL;         // [2,2048,2048]

    static bool init = false;
    static __nv_bfloat16 *pXh, *pXm, *pXl;
    static __nv_bfloat16 *pWqh, *pWqm, *pWql, *pWkh, *pWkm, *pWkl;
    static __nv_bfloat16 *pWvh, *pWvl, *pWoh, *pWol;
    static __nv_bfloat16 *pQh, *pQm, *pQl, *pKh, *pKm, *pKl, *pCh, *pCl;
    static float *pV, *pS;
    if (!init) {
        cudaGetSymbolAddress((void**)&pXh, g_Xhi);  cudaGetSymbolAddress((void**)&pXm, g_Xmd);
        cudaGetSymbolAddress((void**)&pXl, g_Xlo);
        cudaGetSymbolAddress((void**)&pWqh, g_Wqhi); cudaGetSymbolAddress((void**)&pWqm, g_Wqmd);
        cudaGetSymbolAddress((void**)&pWql, g_Wqlo);
        cudaGetSymbolAddress((void**)&pWkh, g_Wkhi); cudaGetSymbolAddress((void**)&pWkm, g_Wkmd);
        cudaGetSymbolAddress((void**)&pWkl, g_Wklo);
        cudaGetSymbolAddress((void**)&pWvh, g_Wvhi); cudaGetSymbolAddress((void**)&pWvl, g_Wvlo);
        cudaGetSymbolAddress((void**)&pWoh, g_Wohi); cudaGetSymbolAddress((void**)&pWol, g_Wolo);
        cudaGetSymbolAddress((void**)&pQh, g_Qhi);   cudaGetSymbolAddress((void**)&pQm, g_Qmd);
        cudaGetSymbolAddress((void**)&pQl, g_Qlo);
        cudaGetSymbolAddress((void**)&pKh, g_Khi);   cudaGetSymbolAddress((void**)&pKm, g_Kmd);
        cudaGetSymbolAddress((void**)&pKl, g_Klo);
        cudaGetSymbolAddress((void**)&pCh, g_Chi);   cudaGetSymbolAddress((void**)&pCl, g_Clo);
        cudaGetSymbolAddress((void**)&pV, g_V);      cudaGetSymbolAddress((void**)&pS, g_S);
        cudaFuncSetAttribute(qkv_gemm_kernel,   cudaFuncAttributeMaxDynamicSharedMemorySize, SMEM_GEMM);
        cudaFuncSetAttribute(proj_gemm_kernel,  cudaFuncAttributeMaxDynamicSharedMemorySize, SMEM_GEMM);
        cudaFuncSetAttribute(score_gemm_kernel, cudaFuncAttributeMaxDynamicSharedMemorySize, SMEM_GEMM);
        init = true;
    }

    split3_kernel<<<2048, 256>>>(x,  pXh, pXm, pXl, MTOT * D_MODEL);
    split3_kernel<<<2048, 256>>>(Wq, pWqh, pWqm, pWql, D_MODEL * D_MODEL);
    split3_kernel<<<2048, 256>>>(Wk, pWkh, pWkm, pWkl, D_MODEL * D_MODEL);
    split2_kernel<<<2048, 256>>>(Wv, pWvh, pWvl, D_MODEL * D_MODEL);
    split2_kernel<<<2048, 256>>>(Wo, pWoh, pWol, D_MODEL * D_MODEL);

    qkv_gemm_kernel<<<dim3(12, MTOT / 128), 256, SMEM_GEMM>>>(
        pXh, pXm, pXl,
        pWqh, pWqm, pWql, bq,
        pWkh, pWkm, pWkl, bk,
        pWvh, pWvl, bv,
        pQh, pQm, pQl, pKh, pKm, pKl, pV);

    score_gemm_kernel<<<dim3(SEQ / 256, SEQ / 128, BHTOT), 256, SMEM_GEMM>>>(
        pQh, pQm, pQl, pKh, pKm, pKl, pS);

    cudaMemsetAsync(attn, 0, (size_t)BATCH * SEQ * SEQ * sizeof(float));

    topk_av_kernel<<<BATCH * NHEADS * SEQ, 256>>>(pS, pV, pCh, pCl, attn);

    proj_gemm_kernel<<<dim3(D_MODEL / 256, MTOT / 128), 256, SMEM_GEMM>>>(
        pCh, pCl, pWoh, pWol, bo, y);
}